// round 1
// baseline (speedup 1.0000x reference)
#include <cuda_runtime.h>

namespace {

constexpr int Bsz = 32768;
constexpr int NIN = 41;
constexpr int NL2 = 4;
constexpr int NRC = 8;
constexpr int WPB = 8;   // warps (batch elements) per block
constexpr unsigned FULL = 0xffffffffu;

__global__ __launch_bounds__(WPB * 32, 2) void pgnet_kernel(
    const float* __restrict__ inp,
    const float* __restrict__ fpg_w,
    const float* __restrict__ fpg_b,
    const float* __restrict__ rpg_w,
    const float* __restrict__ rpg_b,
    const float* __restrict__ pgctrl_w,
    const float* __restrict__ pgctrl_b,
    float* __restrict__ out)
{
    __shared__ float s_wsum[NRC * NIN];     // Wc[r,i] + Wc[r,45+i]
    __shared__ float s_wc2[NRC * 44];       // Wc[r,45+o], zero-padded to 44
    __shared__ float s_pb[NRC];
    __shared__ float s_inp[WPB][NIN + 1];

    const int tid = threadIdx.x;

    // block-shared pgctrl preprocessing
    for (int idx = tid; idx < NRC * 44; idx += WPB * 32) {
        int rr = idx / 44, oo = idx % 44;
        s_wc2[idx] = (oo < NIN) ? pgctrl_w[rr * 86 + 45 + oo] : 0.f;
    }
    for (int idx = tid; idx < NRC * NIN; idx += WPB * 32) {
        int rr = idx / NIN, ii = idx % NIN;
        s_wsum[idx] = pgctrl_w[rr * 86 + ii] + pgctrl_w[rr * 86 + 45 + ii];
    }
    if (tid < NRC) s_pb[tid] = pgctrl_b[tid];

    const int warp = tid >> 5;
    const int lane = tid & 31;
    const int b = blockIdx.x * WPB + warp;   // grid sized exactly: b < Bsz
    const int g = lane >> 3;                 // 0..3
    const int r = lane & 7;                  // 0..7

    if (lane < NIN)      s_inp[warp][lane]      = inp[b * NIN + lane];
    if (lane + 32 < NIN) s_inp[warp][lane + 32] = inp[b * NIN + lane + 32];
    __syncthreads();

    const float* si = s_inp[warp];

    // ---- fpg weights: lane owns (o=g, r); clamp once; dot with inp is
    //      iteration-invariant so hoist it entirely. ----
    float fdot = 0.f;
    {
        const float* fw = fpg_w + (long)b * 1312 + g * 328 + r;
        #pragma unroll
        for (int k = 0; k < NIN; k++) {
            float w = fw[k * 8];
            w = fminf(fmaxf(w, -1.f), 1.f);
            fdot = fmaf(w, si[k], fdot);
        }
    }
    const float fb = fpg_b[b * NL2 + g];

    // ---- rpg weights: lane owns o = g + 4m (m=0..10), fixed r, all i. ----
    float wr[11][4], rb[11];
    {
        const float* rw = rpg_w + (long)b * 1312;
        #pragma unroll
        for (int m = 0; m < 11; m++) {
            int o = g + 4 * m;
            bool valid = (o < NIN);
            int oc = valid ? o : 0;
            #pragma unroll
            for (int i = 0; i < 4; i++) {
                float w = rw[oc * 32 + i * 8 + r];
                w = fminf(fmaxf(w, -1.f), 1.f);
                wr[m][i] = valid ? w : 0.f;
            }
            rb[m] = valid ? rpg_b[b * NIN + oc] : 0.f;
        }
    }

    // ---- A_r: iteration-invariant rc preactivation part ----
    float A = s_pb[r];
    {
        const float* ws = s_wsum + r * NIN;
        #pragma unroll
        for (int i = 0; i < NIN; i++) A = fmaf(si[i], ws[i], A);
    }

    float l1i[11];
    #pragma unroll
    for (int m = 0; m < 11; m++) l1i[m] = 0.f;
    float rc = 0.f, l2v = 0.f;
    float l2all[4];

    #pragma unroll
    for (int it = 0; it < 2; it++) {
        // ---- D_r = sum_o l1i[o] * Wc[r,45+o]  (0 on first iteration) ----
        float D = 0.f;
        const float* wc2 = s_wc2 + r * 44;
        #pragma unroll
        for (int m = 0; m < 11; m++) D = fmaf(l1i[m], wc2[g + 4 * m], D);
        D += __shfl_xor_sync(FULL, D, 8);
        D += __shfl_xor_sync(FULL, D, 16);

        // rc = blur^3( clip(0.4 * leaky(A - D), -0.2, 1) )
        float x = A - D;
        x = (x >= 0.f) ? x : 0.2f * x;
        float v = fminf(fmaxf(0.4f * x, -0.2f), 1.0f);
        #pragma unroll
        for (int t = 0; t < 3; t++) {
            float lv = __shfl_up_sync(FULL, v, 1);
            float rv = __shfl_down_sync(FULL, v, 1);
            lv = (r > 0) ? lv : 0.f;
            rv = (r < 7) ? rv : 0.f;
            v = 0.8f * v + 0.1f * (lv + rv);
        }
        rc = v;

        // ---- fpg -> l2 (dot hoisted; just scale + 8-lane reduce) ----
        float acc = fdot * rc;
        acc += __shfl_xor_sync(FULL, acc, 1);
        acc += __shfl_xor_sync(FULL, acc, 2);
        acc += __shfl_xor_sync(FULL, acc, 4);
        float t2 = fminf(fmaxf(0.1f * (acc + fb), -0.2f), 1.0f);
        #pragma unroll
        for (int t = 0; t < 2; t++) {
            float lv = __shfl_up_sync(FULL, t2, 8);
            float rv = __shfl_down_sync(FULL, t2, 8);
            lv = (g > 0) ? lv : 0.f;
            rv = (g < 3) ? rv : 0.f;
            t2 = 0.8f * t2 + 0.1f * (lv + rv);
        }
        l2v = t2;
        #pragma unroll
        for (int i = 0; i < 4; i++)
            l2all[i] = __shfl_sync(FULL, l2v, i * 8 + r);

        // ---- rpg -> l1i ----
        #pragma unroll
        for (int m = 0; m < 11; m++) {
            float a = 0.f;
            #pragma unroll
            for (int i = 0; i < 4; i++) a = fmaf(wr[m][i], l2all[i], a);
            a *= rc;
            a += __shfl_xor_sync(FULL, a, 1);
            a += __shfl_xor_sync(FULL, a, 2);
            a += __shfl_xor_sync(FULL, a, 4);
            l1i[m] = fminf(fmaxf(a + rb[m], -0.2f), 1.0f);
        }
    }

    // ---- outputs: concat(l1i [B,41], l2 [B,4], rc [B,8]) ----
    if (r == 0) {
        #pragma unroll
        for (int m = 0; m < 11; m++) {
            int o = g + 4 * m;
            if (o < NIN) out[(long)b * NIN + o] = l1i[m];
        }
        out[(long)Bsz * NIN + b * NL2 + g] = l2v;
    }
    if (lane < NRC)
        out[(long)Bsz * (NIN + NL2) + b * NRC + lane] = rc;
}

} // namespace

extern "C" void kernel_launch(void* const* d_in, const int* in_sizes, int n_in,
                              void* d_out, int out_size) {
    pgnet_kernel<<<Bsz / WPB, WPB * 32>>>(
        (const float*)d_in[0],   // inp
        (const float*)d_in[1],   // fpg_w
        (const float*)d_in[2],   // fpg_b
        (const float*)d_in[3],   // rpg_w
        (const float*)d_in[4],   // rpg_b
        (const float*)d_in[5],   // pgctrl_w
        (const float*)d_in[6],   // pgctrl_b
        (float*)d_out);
}

// round 2
// speedup vs baseline: 1.0027x; 1.0027x over previous
#include <cuda_runtime.h>

namespace {

constexpr int Bsz = 32768;
constexpr int NIN = 41;
constexpr int WPB = 8;   // warps (batch elements) per block
constexpr unsigned FULL = 0xffffffffu;

__device__ __forceinline__ float clamp1(float w) {
    return fminf(fmaxf(w, -1.f), 1.f);
}
__device__ __forceinline__ float clipv(float w) {
    return fminf(fmaxf(w, -0.2f), 1.0f);
}

__global__ __launch_bounds__(WPB * 32, 2) void pgnet_kernel(
    const float* __restrict__ inp,
    const float* __restrict__ fpg_w,
    const float* __restrict__ fpg_b,
    const float* __restrict__ rpg_w,
    const float* __restrict__ rpg_b,
    const float* __restrict__ pgctrl_w,
    const float* __restrict__ pgctrl_b,
    float* __restrict__ out)
{
    __shared__ float s_wsum[8 * NIN];      // Wc[r,i] + Wc[r,45+i]
    __shared__ float s_wc2[8 * 44];        // Wc[r,45+o], zero-padded to 44
    __shared__ float s_pb[8];
    __shared__ float s_inp[WPB][44];
    __shared__ float4 s_fpg[WPB][328];     // fpg_w[b], natural layout

    const int tid  = threadIdx.x;
    const int warp = tid >> 5;
    const int lane = tid & 31;
    const int b = blockIdx.x * WPB + warp; // grid sized exactly
    const int q = lane >> 3;               // group 0..3 (g / o%4 role)
    const int j = lane & 7;                // 0..7 (r role)

    // ---- rpg_w: coalesced float4 loads straight into registers ----
    // float4 #n (n = 32s + lane) holds row o = 4s + q, columns c = 4j..4j+3
    const float4* rw4 = (const float4*)(rpg_w + (long)b * 1312);
    float4 w4[11];
    #pragma unroll
    for (int s = 0; s < 11; s++) {
        int n = s * 32 + lane;
        if (n < 328) w4[s] = rw4[n];
        else         w4[s] = make_float4(0.f, 0.f, 0.f, 0.f);
    }

    // ---- fpg_w: coalesced float4 -> shared (per-warp) ----
    const float4* fw4 = (const float4*)(fpg_w + (long)b * 1312);
    #pragma unroll
    for (int s = 0; s < 11; s++) {
        int n = s * 32 + lane;
        if (n < 328) s_fpg[warp][n] = fw4[n];
    }

    // ---- pgctrl preprocessing (block-shared) ----
    for (int idx = tid; idx < 8 * 44; idx += WPB * 32) {
        int rr = idx / 44, oo = idx % 44;
        s_wc2[idx] = (oo < NIN) ? pgctrl_w[rr * 86 + 45 + oo] : 0.f;
    }
    for (int idx = tid; idx < 8 * NIN; idx += WPB * 32) {
        int rr = idx / NIN, ii = idx % NIN;
        s_wsum[idx] = pgctrl_w[rr * 86 + ii] + pgctrl_w[rr * 86 + 45 + ii];
    }
    if (tid < 8) s_pb[tid] = pgctrl_b[tid];

    if (lane < NIN)      s_inp[warp][lane]      = inp[b * NIN + lane];
    if (lane + 32 < NIN) s_inp[warp][lane + 32] = inp[b * NIN + lane + 32];

    // small per-lane loads
    float rb[11];
    #pragma unroll
    for (int s = 0; s < 11; s++) {
        int o = 4 * s + q;
        rb[s] = (o < NIN) ? rpg_b[b * NIN + o] : 0.f;
    }
    const float fb = fpg_b[b * 4 + q];

    __syncthreads();

    // clamp rpg weights once (clip is idempotent, weights fixed)
    #pragma unroll
    for (int s = 0; s < 11; s++) {
        w4[s].x = clamp1(w4[s].x);
        w4[s].y = clamp1(w4[s].y);
        w4[s].z = clamp1(w4[s].z);
        w4[s].w = clamp1(w4[s].w);
    }

    const float* si = s_inp[warp];
    const float* sf = (const float*)&s_fpg[warp][0];

    // ---- hoisted fpg dot: fdot(g=q, r=j) -- conflict-free LDS ----
    float fdot = 0.f;
    #pragma unroll
    for (int k = 0; k < NIN; k++) {
        float w = clamp1(sf[q * 328 + k * 8 + j]);
        fdot = fmaf(w, si[k], fdot);
    }

    // ---- A_j: iteration-invariant rc preactivation ----
    float A = s_pb[j];
    #pragma unroll
    for (int i = 0; i < NIN; i++) A = fmaf(si[i], s_wsum[j * NIN + i], A);

    float l1i[11];
    #pragma unroll
    for (int s = 0; s < 11; s++) l1i[s] = 0.f;
    float rc = 0.f, l2v = 0.f;

    #pragma unroll
    for (int it = 0; it < 2; it++) {
        // ---- D_j = sum_o l1i[o] * Wc[j,45+o] ----
        float D = 0.f;
        #pragma unroll
        for (int s = 0; s < 11; s++)
            D = fmaf(l1i[s], s_wc2[j * 44 + 4 * s + q], D);
        D += __shfl_xor_sync(FULL, D, 8);
        D += __shfl_xor_sync(FULL, D, 16);

        // rc = blur^3( clip(0.4 * leaky(A - D), -0.2, 1) )
        float x = A - D;
        x = (x >= 0.f) ? x : 0.2f * x;
        float v = clipv(0.4f * x);
        #pragma unroll
        for (int t = 0; t < 3; t++) {
            float lv = __shfl_up_sync(FULL, v, 1);
            float rv = __shfl_down_sync(FULL, v, 1);
            lv = (j > 0) ? lv : 0.f;
            rv = (j < 7) ? rv : 0.f;
            v = 0.8f * v + 0.1f * (lv + rv);
        }
        rc = v;

        // ---- fpg -> l2 (dot hoisted; scale + 8-lane reduce + blur^2) ----
        float acc = fdot * rc;
        acc += __shfl_xor_sync(FULL, acc, 1);
        acc += __shfl_xor_sync(FULL, acc, 2);
        acc += __shfl_xor_sync(FULL, acc, 4);
        float t2 = clipv(0.1f * (acc + fb));
        #pragma unroll
        for (int t = 0; t < 2; t++) {
            float lv = __shfl_up_sync(FULL, t2, 8);
            float rv = __shfl_down_sync(FULL, t2, 8);
            lv = (q > 0) ? lv : 0.f;
            rv = (q < 3) ? rv : 0.f;
            t2 = 0.8f * t2 + 0.1f * (lv + rv);
        }
        l2v = t2;

        // ---- per-lane gate products p[t] = l2[i] * rc[r], c = 4j+t ----
        float l2i = __shfl_sync(FULL, l2v, (j >> 1) << 3);
        int rbase = (j & 1) << 2;
        float p0 = l2i * __shfl_sync(FULL, rc, rbase + 0);
        float p1 = l2i * __shfl_sync(FULL, rc, rbase + 1);
        float p2 = l2i * __shfl_sync(FULL, rc, rbase + 2);
        float p3 = l2i * __shfl_sync(FULL, rc, rbase + 3);

        // ---- rpg -> l1i: row o = 4s+q, reduce over j ----
        #pragma unroll
        for (int s = 0; s < 11; s++) {
            float a = w4[s].x * p0;
            a = fmaf(w4[s].y, p1, a);
            a = fmaf(w4[s].z, p2, a);
            a = fmaf(w4[s].w, p3, a);
            a += __shfl_xor_sync(FULL, a, 1);
            a += __shfl_xor_sync(FULL, a, 2);
            a += __shfl_xor_sync(FULL, a, 4);
            l1i[s] = clipv(a + rb[s]);
        }
    }

    // ---- outputs: concat(l1i [B,41], l2 [B,4], rc [B,8]) ----
    if (j == 0) {
        #pragma unroll
        for (int s = 0; s < 11; s++) {
            int o = 4 * s + q;
            if (o < NIN) out[(long)b * NIN + o] = l1i[s];
        }
        out[(long)Bsz * NIN + b * 4 + q] = l2v;
    }
    if (lane < 8)
        out[(long)Bsz * 45 + b * 8 + lane] = rc;
}

} // namespace

extern "C" void kernel_launch(void* const* d_in, const int* in_sizes, int n_in,
                              void* d_out, int out_size) {
    pgnet_kernel<<<Bsz / WPB, WPB * 32>>>(
        (const float*)d_in[0],   // inp
        (const float*)d_in[1],   // fpg_w
        (const float*)d_in[2],   // fpg_b
        (const float*)d_in[3],   // rpg_w
        (const float*)d_in[4],   // rpg_b
        (const float*)d_in[5],   // pgctrl_w
        (const float*)d_in[6],   // pgctrl_b
        (float*)d_out);
}